// round 2
// baseline (speedup 1.0000x reference)
#include <cuda_runtime.h>
#include <math.h>

#define T_FFT 256
#define LOG2M 14
#define MF    16384      // complex FFT length (real length N = 32768)
#define HALF  8192       // MF/2
#define LSEQ  16384
#define NS    64

// ---------------- device scratch (no allocation allowed) --------------------
__device__ float  g_Ab[NS * NS];
__device__ float  g_Bb[NS];
__device__ float  g_Cb[NS];
__device__ float  g_W[128 * NS];
__device__ float  g_V[128 * NS];
__device__ float  g_K[LSEQ];
__device__ float2 g_H[MF + 1];
__device__ float2 g_twC[128];   // e^{-2pi i h/128}
__device__ float2 g_twF[128];   // e^{-2pi i l/16384}
__device__ float2 g_twCN[128];  // e^{-2pi i h/256}
__device__ float2 g_twFN[128];  // e^{-2pi i l/32768}

__device__ __forceinline__ float2 cmul(float2 a, float2 b) {
    return make_float2(a.x * b.x - a.y * b.y, a.x * b.y + a.y * b.x);
}
__device__ __forceinline__ float2 cconj(float2 a) { return make_float2(a.x, -a.y); }

// ---------------- in-place radix-2 FFT, M = 16384, 256 threads --------------
// Forward: DIF, natural -> bit-reversed. Inverse: DIT, bit-reversed -> natural.
template <bool INV>
__device__ void fft16k(float2* s, const float2* tC, const float2* tF) {
    const int tid = threadIdx.x;
    for (int it = 0; it < LOG2M; ++it) {
        const int p  = INV ? (it + 1) : (LOG2M - it);
        const int H  = 1 << (p - 1);
        const int sh = LOG2M - p;
        const int j0 = tid & (H - 1);
        const int x0 = j0 << sh;
        float2 w0 = cmul(tC[x0 >> 7], tF[x0 & 127]);
        if (INV) w0 = cconj(w0);
        float2 w = w0;
        float2 wstep = make_float2(1.f, 0.f);
        const bool rec = (H > T_FFT);
        if (rec) {
            int xs = T_FFT << sh;
            wstep = cmul(tC[xs >> 7], tF[xs & 127]);
            if (INV) wstep = cconj(wstep);
        }
        for (int q = tid; q < HALF; q += T_FFT) {
            int j  = q & (H - 1);
            int i0 = ((q >> (p - 1)) << p) + j;
            int i1 = i0 + H;
            if (!INV) {
                float2 a = s[i0], c = s[i1];
                s[i0] = make_float2(a.x + c.x, a.y + c.y);
                float2 d = make_float2(a.x - c.x, a.y - c.y);
                s[i1] = cmul(d, w);
            } else {
                float2 a = s[i0];
                float2 c = cmul(s[i1], w);
                s[i0] = make_float2(a.x + c.x, a.y + c.y);
                s[i1] = make_float2(a.x - c.x, a.y - c.y);
            }
            if (rec) { if (j + T_FFT >= H) w = w0; else w = cmul(w, wstep); }
        }
        __syncthreads();
    }
}

// ---------------- kernel 1: discretize + twiddles + powers + chains ---------
__global__ __launch_bounds__(256) void k_prep(const float* __restrict__ A,
                                              const float* __restrict__ B,
                                              const float* __restrict__ C,
                                              const float* __restrict__ logstep) {
    extern __shared__ float sm[];
    const int AW = 132;                      // padded row width (129 cols)
    float* aug  = sm;                        // 64*132 = 8448
    float* AbS  = sm + 64 * AW;              // 4096
    float* P1   = AbS + 4096;                // 4096
    float* P2   = P1 + 4096;                 // 4096
    float* vecs = P2 + 4096;                 // 256
    float* fcol = vecs + 256;                // 64
    float* wv = vecs;       float* vv = vecs + 64;
    float* nw = vecs + 128; float* nv = vecs + 192;
    __shared__ int   s_piv;
    __shared__ float s_step;
    const int tid = threadIdx.x;

    if (tid < 128) {
        const double PI = 3.14159265358979323846;
        double sv, cv, ang;
        ang = -2.0 * PI * (double)tid / 128.0;    sincos(ang, &sv, &cv);
        g_twC[tid] = make_float2((float)cv, (float)sv);
        ang = -2.0 * PI * (double)tid / 16384.0;  sincos(ang, &sv, &cv);
        g_twF[tid] = make_float2((float)cv, (float)sv);
        ang = -2.0 * PI * (double)tid / 256.0;    sincos(ang, &sv, &cv);
        g_twCN[tid] = make_float2((float)cv, (float)sv);
        ang = -2.0 * PI * (double)tid / 32768.0;  sincos(ang, &sv, &cv);
        g_twFN[tid] = make_float2((float)cv, (float)sv);
    }
    if (tid == 0) s_step = expf(logstep[0]);
    __syncthreads();
    const float st = s_step;
    const float hs = 0.5f * st;

    // augmented [I - hs*A | I + hs*A | st*B]
    for (int idx = tid; idx < 64 * 129; idx += blockDim.x) {
        int r = idx / 129, c = idx % 129;
        float v;
        if (c < 64)       v = (r == c ? 1.f : 0.f) - hs * A[r * 64 + c];
        else if (c < 128) v = (r == (c - 64) ? 1.f : 0.f) + hs * A[r * 64 + (c - 64)];
        else              v = st * B[r];
        aug[r * AW + c] = v;
    }
    __syncthreads();

    // Gauss-Jordan with partial pivoting
    for (int col = 0; col < 64; ++col) {
        if (tid == 0) {
            int p = col; float best = fabsf(aug[col * AW + col]);
            for (int r = col + 1; r < 64; ++r) {
                float v = fabsf(aug[r * AW + col]);
                if (v > best) { best = v; p = r; }
            }
            s_piv = p;
        }
        __syncthreads();
        int p = s_piv;
        if (p != col) {
            for (int c = tid; c < 129; c += blockDim.x) {
                float t = aug[col * AW + c];
                aug[col * AW + c] = aug[p * AW + c];
                aug[p * AW + c] = t;
            }
        }
        __syncthreads();
        float inv = 1.0f / aug[col * AW + col];
        for (int c = tid; c < 129; c += blockDim.x) aug[col * AW + c] *= inv;
        __syncthreads();
        if (tid < 64) fcol[tid] = aug[tid * AW + col];
        __syncthreads();
        for (int idx = tid; idx < 64 * 129; idx += blockDim.x) {
            int r = idx / 129, c = idx % 129;
            if (r != col) aug[r * AW + c] -= fcol[r] * aug[col * AW + c];
        }
        __syncthreads();
    }

    for (int idx = tid; idx < 4096; idx += blockDim.x) {
        int r = idx >> 6, c = idx & 63;
        float v = aug[r * AW + 64 + c];
        AbS[idx] = v;
        g_Ab[idx] = v;
    }
    if (tid < 64) { g_Bb[tid] = aug[tid * AW + 128]; g_Cb[tid] = C[tid]; }
    __syncthreads();

    // 7 squarings -> Ab^128
    float* src = AbS; float* dst = P1;
    for (int t = 0; t < 7; ++t) {
        for (int idx = tid; idx < 4096; idx += blockDim.x) {
            int r = idx >> 6, c = idx & 63;
            float acc = 0.f;
            #pragma unroll 8
            for (int k = 0; k < 64; ++k) acc += src[r * 64 + k] * src[k * 64 + c];
            dst[idx] = acc;
        }
        __syncthreads();
        src = dst;
        dst = (src == P1) ? P2 : P1;
    }
    float* Abm  = src;
    float* AbmT = dst;
    for (int idx = tid; idx < 4096; idx += blockDim.x) {
        int r = idx >> 6, c = idx & 63;
        AbmT[c * 64 + r] = Abm[r * 64 + c];
    }
    if (tid < 64) wv[tid] = g_Cb[tid];
    else if (tid < 128) vv[tid - 64] = g_Bb[tid - 64];
    __syncthreads();

    // concurrent chains: W (warps 0-1), V (warps 2-3)
    for (int stp = 0; stp < 128; ++stp) {
        if (tid < 64) {
            g_W[stp * 64 + tid] = wv[tid];
            float acc = 0.f;
            #pragma unroll 8
            for (int r = 0; r < 64; ++r) acc += wv[r] * AbS[r * 64 + tid];
            nw[tid] = acc;
        } else if (tid < 128) {
            int r = tid - 64;
            g_V[stp * 64 + r] = vv[r];
            float acc = 0.f;
            #pragma unroll 8
            for (int c = 0; c < 64; ++c) acc += AbmT[c * 64 + r] * vv[c];
            nv[r] = acc;
        }
        __syncthreads();
        if (tid < 64) wv[tid] = nw[tid];
        else if (tid < 128) vv[tid - 64] = nv[tid - 64];
        __syncthreads();
    }
}

// ---------------- kernel 2: K[128 i + j] = W[j] . V[i] ----------------------
__global__ __launch_bounds__(128) void k_K() {
    int il = blockIdx.x * 128 + threadIdx.x;
    int j = il & 127, i = il >> 7;
    float acc = 0.f;
    #pragma unroll 8
    for (int r = 0; r < 64; ++r) acc += g_W[j * 64 + r] * g_V[i * 64 + r];
    g_K[il] = acc;
}

// ---------------- kernel 3: H = rfft(K, 32768) / MF -------------------------
__global__ __launch_bounds__(T_FFT) void k_kfft() {
    extern __shared__ float2 sh2[];
    float2* s   = sh2;
    float2* tC  = s + MF;
    float2* tF  = tC + 128;
    float2* tCN = tF + 128;
    float2* tFN = tCN + 128;
    const int tid = threadIdx.x;
    if (tid < 128) {
        tC[tid] = g_twC[tid]; tF[tid] = g_twF[tid];
        tCN[tid] = g_twCN[tid]; tFN[tid] = g_twFN[tid];
    }
    const float2* K2 = reinterpret_cast<const float2*>(g_K);
    for (int n = tid; n < MF; n += T_FFT)
        s[n] = (n < HALF) ? K2[n] : make_float2(0.f, 0.f);
    __syncthreads();
    fft16k<false>(s, tC, tF);

    const float sc = 1.0f / (float)MF;
    if (tid == 0) {
        float2 Z0 = s[0];
        g_H[0]  = make_float2((Z0.x + Z0.y) * sc, 0.f);
        g_H[MF] = make_float2((Z0.x - Z0.y) * sc, 0.f);
    }
    for (int k = tid + 1; k <= HALF; k += T_FFT) {
        int rk = __brev(k) >> (32 - LOG2M);
        int rm = __brev(MF - k) >> (32 - LOG2M);
        float2 a  = s[rk];
        float2 bb = cconj(s[rm]);
        float2 E  = make_float2(0.5f * (a.x + bb.x), 0.5f * (a.y + bb.y));
        float2 Od = make_float2(0.5f * (a.x - bb.x), 0.5f * (a.y - bb.y));
        float2 wN = cmul(tCN[k >> 7], tFN[k & 127]);
        float2 g  = make_float2(wN.y, -wN.x);        // -i * e^{-2pi i k/N}
        float2 gOd = cmul(g, Od);
        g_H[k]      = make_float2((E.x + gOd.x) * sc, (E.y + gOd.y) * sc);
        g_H[MF - k] = make_float2((E.x - gOd.x) * sc, -(E.y - gOd.y) * sc);
    }
}

// ---------------- kernel 4: per-row FFT conv + D*u --------------------------
__global__ __launch_bounds__(T_FFT) void k_conv(const float* __restrict__ u,
                                                const float* __restrict__ Dp,
                                                float* __restrict__ out) {
    extern __shared__ float2 sh2[];
    float2* s   = sh2;
    float2* tC  = s + MF;
    float2* tF  = tC + 128;
    float2* tCN = tF + 128;
    float2* tFN = tCN + 128;
    const int tid = threadIdx.x;
    const int b = blockIdx.x;
    if (tid < 128) {
        tC[tid] = g_twC[tid]; tF[tid] = g_twF[tid];
        tCN[tid] = g_twCN[tid]; tFN[tid] = g_twFN[tid];
    }
    const float2* u2 = reinterpret_cast<const float2*>(u) + (size_t)b * HALF;
    for (int n = tid; n < MF; n += T_FFT)
        s[n] = (n < HALF) ? u2[n] : make_float2(0.f, 0.f);
    __syncthreads();

    fft16k<false>(s, tC, tF);

    // spectral: unpack rfft bins, multiply by H, repack for inverse (in bitrev)
    if (tid == 0) {
        float2 Z0 = s[0];
        float X0 = Z0.x + Z0.y;
        float XM = Z0.x - Z0.y;
        float Y0 = X0 * g_H[0].x;
        float YM = XM * g_H[MF].x;
        s[0] = make_float2(0.5f * (Y0 + YM), 0.5f * (Y0 - YM));
    }
    for (int k = tid + 1; k <= HALF; k += T_FFT) {
        int rk = __brev(k) >> (32 - LOG2M);
        int rm = __brev(MF - k) >> (32 - LOG2M);
        float2 a  = s[rk];
        float2 bb = cconj(s[rm]);
        float2 E  = make_float2(0.5f * (a.x + bb.x), 0.5f * (a.y + bb.y));
        float2 Od = make_float2(0.5f * (a.x - bb.x), 0.5f * (a.y - bb.y));
        float2 wN = cmul(tCN[k >> 7], tFN[k & 127]);
        float2 g  = make_float2(wN.y, -wN.x);        // -i * w
        float2 gOd = cmul(g, Od);
        float2 Xk = make_float2(E.x + gOd.x, E.y + gOd.y);
        float2 Xm = make_float2(E.x - gOd.x, -(E.y - gOd.y));
        float2 Yk = cmul(Xk, g_H[k]);
        float2 Ym = cmul(Xm, g_H[MF - k]);
        float2 cYm = cconj(Ym);
        float2 Ep  = make_float2(0.5f * (Yk.x + cYm.x), 0.5f * (Yk.y + cYm.y));
        float2 Dd  = make_float2(0.5f * (Yk.x - cYm.x), 0.5f * (Yk.y - cYm.y));
        // Z'[k] = E' + conj(g)*D ;  Z'[M-k] = conj(E') - g*conj(D)
        float2 t1 = cmul(cconj(g), Dd);
        float2 t2 = cmul(g, cconj(Dd));
        s[rk] = make_float2(Ep.x + t1.x, Ep.y + t1.y);
        s[rm] = make_float2(Ep.x - t2.x, -Ep.y - t2.y);
    }
    __syncthreads();

    fft16k<true>(s, tC, tF);

    const float Dv = Dp[0];
    float2* o2 = reinterpret_cast<float2*>(out) + (size_t)b * HALF;
    for (int n = tid; n < HALF; n += T_FFT) {
        float2 z  = s[n];
        float2 uu = u2[n];
        o2[n] = make_float2(z.x + Dv * uu.x, z.y + Dv * uu.y);
    }
}

// ---------------- launch ----------------------------------------------------
extern "C" void kernel_launch(void* const* d_in, const int* in_sizes, int n_in,
                              void* d_out, int out_size) {
    const float* u  = (const float*)d_in[0];
    const float* A  = (const float*)d_in[1];
    const float* B  = (const float*)d_in[2];
    const float* C  = (const float*)d_in[3];
    const float* D  = (const float*)d_in[4];
    const float* ls = (const float*)d_in[5];
    float* out = (float*)d_out;

    const int smemPrep = (64 * 132 + 3 * 4096 + 256 + 64) * (int)sizeof(float);
    const int smemFFT  = (MF + 4 * 128) * (int)sizeof(float2);

    cudaFuncSetAttribute(k_prep, cudaFuncAttributeMaxDynamicSharedMemorySize, smemPrep);
    cudaFuncSetAttribute(k_kfft, cudaFuncAttributeMaxDynamicSharedMemorySize, smemFFT);
    cudaFuncSetAttribute(k_conv, cudaFuncAttributeMaxDynamicSharedMemorySize, smemFFT);

    k_prep<<<1, 256, smemPrep>>>(A, B, C, ls);
    k_K<<<128, 128>>>();
    k_kfft<<<1, T_FFT, smemFFT>>>();
    k_conv<<<512, T_FFT, smemFFT>>>(u, D, out);
}

// round 3
// speedup vs baseline: 1.8666x; 1.8666x over previous
#include <cuda_runtime.h>
#include <math.h>

#define T_FFT 512
#define LOG2M 14
#define MF    16384      // complex FFT length (real length N = 32768)
#define HALF  8192       // MF/2
#define LSEQ  16384
#define QB    4096       // MF/4 butterflies per radix-4 stage
#define PADI(i) ((i) + ((i) >> 4))

// ---------------- device scratch ----------------
__device__ float  g_W[128 * 64];
__device__ float  g_V[128 * 64];
__device__ float  g_K[LSEQ];
__device__ float2 g_H[MF + 1];
__device__ float2 g_twC[128];   // e^{-2pi i h/128}
__device__ float2 g_twF[128];   // e^{-2pi i l/16384}
__device__ float2 g_twCN[128];  // e^{-2pi i h/256}
__device__ float2 g_twFN[128];  // e^{-2pi i l/32768}

__device__ __forceinline__ float2 cmul(float2 a, float2 b) {
    return make_float2(a.x * b.x - a.y * b.y, a.x * b.y + a.y * b.x);
}
__device__ __forceinline__ float2 cconj(float2 a) { return make_float2(a.x, -a.y); }
__device__ __forceinline__ float2 cadd(float2 a, float2 b) { return make_float2(a.x + b.x, a.y + b.y); }
__device__ __forceinline__ float2 csub(float2 a, float2 b) { return make_float2(a.x - b.x, a.y - b.y); }
__device__ __forceinline__ float2 cmulni(float2 a) { return make_float2(a.y, -a.x); }  // -i*a
__device__ __forceinline__ float2 cmuli(float2 a)  { return make_float2(-a.y, a.x); }  // +i*a

// digit-reverse base-4 of a 14-bit index
__device__ __forceinline__ int rev4_14(int k) {
    unsigned br = __brev((unsigned)k) >> 18;
    return (int)(((br & 0x2AAAu) >> 1) | ((br & 0x1555u) << 1));
}

__constant__ float2 c_w16[4] = {
    {1.0f, 0.0f},
    {0.9238795325f, -0.3826834324f},
    {0.7071067812f, -0.7071067812f},
    {0.3826834324f, -0.9238795325f}
};

// ------------- radix-4 FFT, M=16384, 512 threads, padded smem ---------------
// Forward DIF: natural -> base-4 digit-reversed. Inverse DIT: digit-rev -> natural.
template <bool INV>
__device__ void fft16k4(float2* s, const float2* tC, const float2* tF) {
    const int tid = threadIdx.x;
    if (!INV) {
        #pragma unroll
        for (int st = 0; st < 5; ++st) {
            const int lg = 12 - 2 * st;          // 12,10,8,6,4
            const int H = 1 << lg;
            #pragma unroll
            for (int it = 0; it < QB / T_FFT; ++it) {
                int q = tid + it * T_FFT;
                int j = q & (H - 1);
                int i0 = ((q >> lg) << (lg + 2)) + j;
                float2 a = s[PADI(i0)], b = s[PADI(i0 + H)];
                float2 c = s[PADI(i0 + 2 * H)], d = s[PADI(i0 + 3 * H)];
                float2 y0 = cadd(a, c), y1 = csub(a, c);
                float2 y2 = cadd(b, d), y3 = csub(b, d);
                int x = j << (12 - lg);
                float2 w1 = cmul(tC[x >> 7], tF[x & 127]);
                float2 w2 = cmul(w1, w1), w3 = cmul(w2, w1);
                float2 m3 = cmulni(y3);
                s[PADI(i0)]         = cadd(y0, y2);
                s[PADI(i0 + H)]     = cmul(cadd(y1, m3), w1);
                s[PADI(i0 + 2 * H)] = cmul(csub(y0, y2), w2);
                s[PADI(i0 + 3 * H)] = cmul(csub(y1, m3), w3);
            }
            __syncthreads();
        }
        // fused 16-point tail (spans 4 and 1), per 16-element tile
        #pragma unroll
        for (int it = 0; it < (MF / 16) / T_FFT; ++it) {
            int m = tid + it * T_FFT;
            int base = 16 * m;
            float2 v[16];
            #pragma unroll
            for (int e = 0; e < 16; ++e) v[e] = s[PADI(base + e)];
            #pragma unroll
            for (int j = 0; j < 4; ++j) {   // span 4
                float2 a = v[j], b = v[j + 4], c = v[j + 8], d = v[j + 12];
                float2 y0 = cadd(a, c), y1 = csub(a, c);
                float2 y2 = cadd(b, d), y3 = csub(b, d);
                float2 w1 = c_w16[j];
                float2 w2 = cmul(w1, w1), w3 = cmul(w2, w1);
                float2 m3 = cmulni(y3);
                v[j]      = cadd(y0, y2);
                v[j + 4]  = cmul(cadd(y1, m3), w1);
                v[j + 8]  = cmul(csub(y0, y2), w2);
                v[j + 12] = cmul(csub(y1, m3), w3);
            }
            #pragma unroll
            for (int g = 0; g < 4; ++g) {   // span 1, twiddle-free
                float2 a = v[4 * g], b = v[4 * g + 1], c = v[4 * g + 2], d = v[4 * g + 3];
                float2 y0 = cadd(a, c), y1 = csub(a, c);
                float2 y2 = cadd(b, d), y3 = csub(b, d);
                float2 m3 = cmulni(y3);
                v[4 * g]     = cadd(y0, y2);
                v[4 * g + 1] = cadd(y1, m3);
                v[4 * g + 2] = csub(y0, y2);
                v[4 * g + 3] = csub(y1, m3);
            }
            #pragma unroll
            for (int e = 0; e < 16; ++e) s[PADI(base + e)] = v[e];
        }
        __syncthreads();
    } else {
        // fused 16-point head (spans 1 and 4)
        #pragma unroll
        for (int it = 0; it < (MF / 16) / T_FFT; ++it) {
            int m = tid + it * T_FFT;
            int base = 16 * m;
            float2 v[16];
            #pragma unroll
            for (int e = 0; e < 16; ++e) v[e] = s[PADI(base + e)];
            #pragma unroll
            for (int g = 0; g < 4; ++g) {   // span 1, twiddle-free
                float2 b0 = v[4 * g], b1 = v[4 * g + 1], b2 = v[4 * g + 2], b3 = v[4 * g + 3];
                float2 y0 = cadd(b0, b2), y1 = csub(b0, b2);
                float2 y2 = cadd(b1, b3), y3 = cmuli(csub(b1, b3));
                v[4 * g]     = cadd(y0, y2);
                v[4 * g + 1] = cadd(y1, y3);
                v[4 * g + 2] = csub(y0, y2);
                v[4 * g + 3] = csub(y1, y3);
            }
            #pragma unroll
            for (int j = 0; j < 4; ++j) {   // span 4, conj twiddles
                float2 w1 = cconj(c_w16[j]);
                float2 w2 = cmul(w1, w1), w3 = cmul(w2, w1);
                float2 b0 = v[j];
                float2 t1 = cmul(v[j + 4], w1);
                float2 t2 = cmul(v[j + 8], w2);
                float2 t3 = cmul(v[j + 12], w3);
                float2 y0 = cadd(b0, t2), y1 = csub(b0, t2);
                float2 y2 = cadd(t1, t3), y3 = cmuli(csub(t1, t3));
                v[j]      = cadd(y0, y2);
                v[j + 4]  = cadd(y1, y3);
                v[j + 8]  = csub(y0, y2);
                v[j + 12] = csub(y1, y3);
            }
            #pragma unroll
            for (int e = 0; e < 16; ++e) s[PADI(base + e)] = v[e];
        }
        __syncthreads();
        #pragma unroll
        for (int st = 0; st < 5; ++st) {
            const int lg = 4 + 2 * st;           // 4,6,8,10,12
            const int H = 1 << lg;
            #pragma unroll
            for (int it = 0; it < QB / T_FFT; ++it) {
                int q = tid + it * T_FFT;
                int j = q & (H - 1);
                int i0 = ((q >> lg) << (lg + 2)) + j;
                int x = j << (12 - lg);
                float2 w1 = cconj(cmul(tC[x >> 7], tF[x & 127]));
                float2 w2 = cmul(w1, w1), w3 = cmul(w2, w1);
                float2 b0 = s[PADI(i0)];
                float2 t1 = cmul(s[PADI(i0 + H)], w1);
                float2 t2 = cmul(s[PADI(i0 + 2 * H)], w2);
                float2 t3 = cmul(s[PADI(i0 + 3 * H)], w3);
                float2 y0 = cadd(b0, t2), y1 = csub(b0, t2);
                float2 y2 = cadd(t1, t3), y3 = cmuli(csub(t1, t3));
                s[PADI(i0)]         = cadd(y0, y2);
                s[PADI(i0 + H)]     = cadd(y1, y3);
                s[PADI(i0 + 2 * H)] = csub(y0, y2);
                s[PADI(i0 + 3 * H)] = csub(y1, y3);
            }
            __syncthreads();
        }
    }
}

// ---------------- kernel 1: discretize + twiddles + doubling chains ---------
__global__ __launch_bounds__(256) void k_prep(const float* __restrict__ A,
                                              const float* __restrict__ B,
                                              const float* __restrict__ C,
                                              const float* __restrict__ logstep) {
    extern __shared__ float sm[];
    const int AW = 132;
    float* aug = sm;                 // 64*132 = 8448
    float* W   = aug + 64 * AW;      // 8192
    float* V   = W + 8192;           // 8192
    float* S0  = V + 8192;           // 4096
    float* S1  = S0 + 4096;          // 4096
    float* ST  = S1 + 4096;          // 4096
    float* fcol = ST + 4096;         // 64
    __shared__ float s_step, s_inv;
    const int tid = threadIdx.x;

    if (tid < 128) {
        const double PI = 3.14159265358979323846;
        double sv, cv, ang;
        ang = -2.0 * PI * (double)tid / 128.0;    sincos(ang, &sv, &cv);
        g_twC[tid] = make_float2((float)cv, (float)sv);
        ang = -2.0 * PI * (double)tid / 16384.0;  sincos(ang, &sv, &cv);
        g_twF[tid] = make_float2((float)cv, (float)sv);
        ang = -2.0 * PI * (double)tid / 256.0;    sincos(ang, &sv, &cv);
        g_twCN[tid] = make_float2((float)cv, (float)sv);
        ang = -2.0 * PI * (double)tid / 32768.0;  sincos(ang, &sv, &cv);
        g_twFN[tid] = make_float2((float)cv, (float)sv);
    }
    if (tid == 0) s_step = expf(logstep[0]);
    __syncthreads();
    const float st = s_step;
    const float hs = 0.5f * st;

    // augmented [I - hs*A | I + hs*A | st*B]
    for (int idx = tid; idx < 64 * 129; idx += 256) {
        int r = idx / 129, c = idx % 129;
        float v;
        if (c < 64)       v = (r == c ? 1.f : 0.f) - hs * A[r * 64 + c];
        else if (c < 128) v = (r == (c - 64) ? 1.f : 0.f) + hs * A[r * 64 + (c - 64)];
        else              v = st * B[r];
        aug[r * AW + c] = v;
    }
    __syncthreads();

    // Gauss-Jordan, no pivoting (I - hs*A is diagonally dominant)
    const int gr = tid >> 2;         // row 0..63
    const int gc0 = tid & 3;         // col phase
    for (int col = 0; col < 64; ++col) {
        if (tid == 0) s_inv = 1.0f / aug[col * AW + col];
        __syncthreads();
        float inv = s_inv;
        for (int c = tid; c < 129; c += 256) aug[col * AW + c] *= inv;
        if (tid < 64) fcol[tid] = (tid == col) ? 0.f : aug[tid * AW + col];
        __syncthreads();
        float f = fcol[gr];
        for (int c = gc0; c < 129; c += 4)
            aug[gr * AW + c] -= f * aug[col * AW + c];
        __syncthreads();
    }

    // S0 = Ab = right half; V[0] = Bb; W[0] = Cb
    for (int idx = tid; idx < 4096; idx += 256) {
        int r = idx >> 6, c = idx & 63;
        S0[idx] = aug[r * AW + 64 + c];
    }
    if (tid < 64) { V[tid] = aug[tid * AW + 128]; W[tid] = C[tid]; }
    __syncthreads();

    float* S = S0; float* Sn = S1;
    const int r0 = (tid >> 4) << 2;  // 0..60 step 4
    const int c4 = tid & 15;         // float4 col index

    // W phase: t = 0..6 (expand W, then square S). After: W full, S = Ab^128.
    for (int t = 0; t < 7; ++t) {
        int rows = 1 << t;
        for (int o = tid; o < rows * 64; o += 256) {
            int j = o >> 6, c = o & 63;
            float acc = 0.f;
            #pragma unroll 8
            for (int r = 0; r < 64; ++r) acc += W[j * 64 + r] * S[r * 64 + c];
            W[(j + rows) * 64 + c] = acc;
        }
        __syncthreads();
        // S^2 with 4x4 register tile + float4 loads; also write transpose
        {
            const float4* Sv = (const float4*)S;
            float4 acc0 = {0,0,0,0}, acc1 = {0,0,0,0}, acc2 = {0,0,0,0}, acc3 = {0,0,0,0};
            #pragma unroll 4
            for (int kk = 0; kk < 16; ++kk) {
                float4 b0 = Sv[(4 * kk + 0) * 16 + c4];
                float4 b1 = Sv[(4 * kk + 1) * 16 + c4];
                float4 b2 = Sv[(4 * kk + 2) * 16 + c4];
                float4 b3 = Sv[(4 * kk + 3) * 16 + c4];
                float4 a0 = Sv[(r0 + 0) * 16 + kk];
                float4 a1 = Sv[(r0 + 1) * 16 + kk];
                float4 a2 = Sv[(r0 + 2) * 16 + kk];
                float4 a3 = Sv[(r0 + 3) * 16 + kk];
                #define UPD(ACC, AV) \
                    ACC.x += AV.x*b0.x + AV.y*b1.x + AV.z*b2.x + AV.w*b3.x; \
                    ACC.y += AV.x*b0.y + AV.y*b1.y + AV.z*b2.y + AV.w*b3.y; \
                    ACC.z += AV.x*b0.z + AV.y*b1.z + AV.z*b2.z + AV.w*b3.z; \
                    ACC.w += AV.x*b0.w + AV.y*b1.w + AV.z*b2.w + AV.w*b3.w;
                UPD(acc0, a0) UPD(acc1, a1) UPD(acc2, a2) UPD(acc3, a3)
                #undef UPD
            }
            __syncthreads();
            float4* Snv = (float4*)Sn;
            Snv[(r0 + 0) * 16 + c4] = acc0;
            Snv[(r0 + 1) * 16 + c4] = acc1;
            Snv[(r0 + 2) * 16 + c4] = acc2;
            Snv[(r0 + 3) * 16 + c4] = acc3;
            int c0 = c4 << 2;
            float accs[4][4] = {{acc0.x,acc0.y,acc0.z,acc0.w},{acc1.x,acc1.y,acc1.z,acc1.w},
                                {acc2.x,acc2.y,acc2.z,acc2.w},{acc3.x,acc3.y,acc3.z,acc3.w}};
            #pragma unroll
            for (int i = 0; i < 4; ++i)
                #pragma unroll
                for (int j2 = 0; j2 < 4; ++j2)
                    ST[(c0 + j2) * 64 + (r0 + i)] = accs[i][j2];
        }
        __syncthreads();
        float* tmp = S; S = Sn; Sn = tmp;
    }

    // V phase: m = 0..6 (expand V with S = Ab^(128*2^m) via ST, then square)
    for (int m = 0; m < 7; ++m) {
        int rows = 1 << m;
        for (int o = tid; o < rows * 64; o += 256) {
            int i = o >> 6, r = o & 63;
            float acc = 0.f;
            #pragma unroll 8
            for (int c = 0; c < 64; ++c) acc += ST[c * 64 + r] * V[i * 64 + c];
            V[(i + rows) * 64 + r] = acc;
        }
        __syncthreads();
        if (m == 6) break;
        {
            const float4* Sv = (const float4*)S;
            float4 acc0 = {0,0,0,0}, acc1 = {0,0,0,0}, acc2 = {0,0,0,0}, acc3 = {0,0,0,0};
            #pragma unroll 4
            for (int kk = 0; kk < 16; ++kk) {
                float4 b0 = Sv[(4 * kk + 0) * 16 + c4];
                float4 b1 = Sv[(4 * kk + 1) * 16 + c4];
                float4 b2 = Sv[(4 * kk + 2) * 16 + c4];
                float4 b3 = Sv[(4 * kk + 3) * 16 + c4];
                float4 a0 = Sv[(r0 + 0) * 16 + kk];
                float4 a1 = Sv[(r0 + 1) * 16 + kk];
                float4 a2 = Sv[(r0 + 2) * 16 + kk];
                float4 a3 = Sv[(r0 + 3) * 16 + kk];
                #define UPD(ACC, AV) \
                    ACC.x += AV.x*b0.x + AV.y*b1.x + AV.z*b2.x + AV.w*b3.x; \
                    ACC.y += AV.x*b0.y + AV.y*b1.y + AV.z*b2.y + AV.w*b3.y; \
                    ACC.z += AV.x*b0.z + AV.y*b1.z + AV.z*b2.z + AV.w*b3.z; \
                    ACC.w += AV.x*b0.w + AV.y*b1.w + AV.z*b2.w + AV.w*b3.w;
                UPD(acc0, a0) UPD(acc1, a1) UPD(acc2, a2) UPD(acc3, a3)
                #undef UPD
            }
            __syncthreads();
            float4* Snv = (float4*)Sn;
            Snv[(r0 + 0) * 16 + c4] = acc0;
            Snv[(r0 + 1) * 16 + c4] = acc1;
            Snv[(r0 + 2) * 16 + c4] = acc2;
            Snv[(r0 + 3) * 16 + c4] = acc3;
            int c0 = c4 << 2;
            float accs[4][4] = {{acc0.x,acc0.y,acc0.z,acc0.w},{acc1.x,acc1.y,acc1.z,acc1.w},
                                {acc2.x,acc2.y,acc2.z,acc2.w},{acc3.x,acc3.y,acc3.z,acc3.w}};
            #pragma unroll
            for (int i = 0; i < 4; ++i)
                #pragma unroll
                for (int j2 = 0; j2 < 4; ++j2)
                    ST[(c0 + j2) * 64 + (r0 + i)] = accs[i][j2];
        }
        __syncthreads();
        float* tmp = S; S = Sn; Sn = tmp;
    }
    __syncthreads();

    for (int idx = tid; idx < 8192; idx += 256) {
        g_W[idx] = W[idx];
        g_V[idx] = V[idx];
    }
}

// ---------------- kernel 2: K[128 i + j] = W[j] . V[i] ----------------------
__global__ __launch_bounds__(128) void k_K() {
    int il = blockIdx.x * 128 + threadIdx.x;
    int j = il & 127, i = il >> 7;
    float acc = 0.f;
    #pragma unroll 8
    for (int r = 0; r < 64; ++r) acc += g_W[j * 64 + r] * g_V[i * 64 + r];
    g_K[il] = acc;
}

// ---------------- kernel 3: H = rfft(K, 32768) / MF -------------------------
__global__ __launch_bounds__(T_FFT) void k_kfft() {
    extern __shared__ float2 sh2[];
    float2* s   = sh2;
    float2* tC  = s + 17408;
    float2* tF  = tC + 128;
    float2* tCN = tF + 128;
    float2* tFN = tCN + 128;
    const int tid = threadIdx.x;
    if (tid < 128) {
        tC[tid] = g_twC[tid]; tF[tid] = g_twF[tid];
        tCN[tid] = g_twCN[tid]; tFN[tid] = g_twFN[tid];
    }
    const float2* K2 = reinterpret_cast<const float2*>(g_K);
    for (int n = tid; n < MF; n += T_FFT)
        s[PADI(n)] = (n < HALF) ? K2[n] : make_float2(0.f, 0.f);
    __syncthreads();
    fft16k4<false>(s, tC, tF);

    const float sc = 1.0f / (float)MF;
    if (tid == 0) {
        float2 Z0 = s[PADI(0)];
        g_H[0]  = make_float2((Z0.x + Z0.y) * sc, 0.f);
        g_H[MF] = make_float2((Z0.x - Z0.y) * sc, 0.f);
    }
    for (int k = tid + 1; k <= HALF; k += T_FFT) {
        int rk = PADI(rev4_14(k));
        int rm = PADI(rev4_14(MF - k));
        float2 a  = s[rk];
        float2 bb = cconj(s[rm]);
        float2 E  = make_float2(0.5f * (a.x + bb.x), 0.5f * (a.y + bb.y));
        float2 Od = make_float2(0.5f * (a.x - bb.x), 0.5f * (a.y - bb.y));
        float2 wN = cmul(tCN[k >> 7], tFN[k & 127]);
        float2 g  = make_float2(wN.y, -wN.x);
        float2 gOd = cmul(g, Od);
        g_H[k]      = make_float2((E.x + gOd.x) * sc, (E.y + gOd.y) * sc);
        g_H[MF - k] = make_float2((E.x - gOd.x) * sc, -(E.y - gOd.y) * sc);
    }
}

// ---------------- kernel 4: per-row FFT conv + D*u --------------------------
__global__ __launch_bounds__(T_FFT) void k_conv(const float* __restrict__ u,
                                                const float* __restrict__ Dp,
                                                float* __restrict__ out) {
    extern __shared__ float2 sh2[];
    float2* s   = sh2;
    float2* tC  = s + 17408;
    float2* tF  = tC + 128;
    float2* tCN = tF + 128;
    float2* tFN = tCN + 128;
    const int tid = threadIdx.x;
    const int b = blockIdx.x;
    if (tid < 128) {
        tC[tid] = g_twC[tid]; tF[tid] = g_twF[tid];
        tCN[tid] = g_twCN[tid]; tFN[tid] = g_twFN[tid];
    }
    const float2* u2 = reinterpret_cast<const float2*>(u) + (size_t)b * HALF;
    for (int n = tid; n < MF; n += T_FFT)
        s[PADI(n)] = (n < HALF) ? u2[n] : make_float2(0.f, 0.f);
    __syncthreads();

    fft16k4<false>(s, tC, tF);

    if (tid == 0) {
        float2 Z0 = s[PADI(0)];
        float X0 = Z0.x + Z0.y;
        float XM = Z0.x - Z0.y;
        float Y0 = X0 * g_H[0].x;
        float YM = XM * g_H[MF].x;
        s[PADI(0)] = make_float2(0.5f * (Y0 + YM), 0.5f * (Y0 - YM));
    }
    for (int k = tid + 1; k <= HALF; k += T_FFT) {
        int rk = PADI(rev4_14(k));
        int rm = PADI(rev4_14(MF - k));
        float2 a  = s[rk];
        float2 bb = cconj(s[rm]);
        float2 E  = make_float2(0.5f * (a.x + bb.x), 0.5f * (a.y + bb.y));
        float2 Od = make_float2(0.5f * (a.x - bb.x), 0.5f * (a.y - bb.y));
        float2 wN = cmul(tCN[k >> 7], tFN[k & 127]);
        float2 g  = make_float2(wN.y, -wN.x);
        float2 gOd = cmul(g, Od);
        float2 Xk = make_float2(E.x + gOd.x, E.y + gOd.y);
        float2 Xm = make_float2(E.x - gOd.x, -(E.y - gOd.y));
        float2 Yk = cmul(Xk, g_H[k]);
        float2 Ym = cmul(Xm, g_H[MF - k]);
        float2 cYm = cconj(Ym);
        float2 Ep  = make_float2(0.5f * (Yk.x + cYm.x), 0.5f * (Yk.y + cYm.y));
        float2 Dd  = make_float2(0.5f * (Yk.x - cYm.x), 0.5f * (Yk.y - cYm.y));
        float2 t1 = cmul(cconj(g), Dd);
        float2 t2 = cmul(g, cconj(Dd));
        s[rk] = make_float2(Ep.x + t1.x, Ep.y + t1.y);
        s[rm] = make_float2(Ep.x - t2.x, -Ep.y - t2.y);
    }
    __syncthreads();

    fft16k4<true>(s, tC, tF);

    const float Dv = Dp[0];
    float2* o2 = reinterpret_cast<float2*>(out) + (size_t)b * HALF;
    for (int n = tid; n < HALF; n += T_FFT) {
        float2 z  = s[PADI(n)];
        float2 uu = u2[n];
        o2[n] = make_float2(z.x + Dv * uu.x, z.y + Dv * uu.y);
    }
}

// ---------------- launch ----------------------------------------------------
extern "C" void kernel_launch(void* const* d_in, const int* in_sizes, int n_in,
                              void* d_out, int out_size) {
    const float* u  = (const float*)d_in[0];
    const float* A  = (const float*)d_in[1];
    const float* B  = (const float*)d_in[2];
    const float* C  = (const float*)d_in[3];
    const float* D  = (const float*)d_in[4];
    const float* ls = (const float*)d_in[5];
    float* out = (float*)d_out;

    const int smemPrep = (64 * 132 + 2 * 8192 + 3 * 4096 + 64) * (int)sizeof(float);
    const int smemFFT  = (17408 + 4 * 128) * (int)sizeof(float2);

    cudaFuncSetAttribute(k_prep, cudaFuncAttributeMaxDynamicSharedMemorySize, smemPrep);
    cudaFuncSetAttribute(k_kfft, cudaFuncAttributeMaxDynamicSharedMemorySize, smemFFT);
    cudaFuncSetAttribute(k_conv, cudaFuncAttributeMaxDynamicSharedMemorySize, smemFFT);

    k_prep<<<1, 256, smemPrep>>>(A, B, C, ls);
    k_K<<<128, 128>>>();
    k_kfft<<<1, T_FFT, smemFFT>>>();
    k_conv<<<512, T_FFT, smemFFT>>>(u, D, out);
}